// round 3
// baseline (speedup 1.0000x reference)
#include <cuda_runtime.h>
#include <cuda_bf16.h>
#include <math.h>

// Problem constants (fixed by setup_inputs)
#define NPTS 32768
#define NV   10475
#define NJ   55
#define KNN  6

// Scratch (no cudaMalloc allowed).
__device__ int   g_knn_idx[NPTS * KNN];
__device__ float g_knn_d  [NPTS * KNN];

// ---------------------------------------------------------------------------
// Kernel 1: fused KNN, reference-rounding-correlated distance.
//   cross = fma(pz,tz, fma(py,ty, fl(px*tx)))      (cublas k-ordered fma)
//   t2/p2 = fl(fl(fl(x^2)+fl(y^2))+fl(z^2))        (square-then-reduce)
//   d2    = fma(-2, cross, fl(p2+t2))              (== fl((p2+t2) - 2*cross))
// One thread = one query point; templates staged in smem as {x,y,z,t2}.
// ---------------------------------------------------------------------------
extern "C" __global__ void __launch_bounds__(256, 1)
knn_kernel(const float* __restrict__ pts,      // (N,3)
           const float* __restrict__ tpts)     // (V,3)
{
    extern __shared__ float4 st[];   // NV float4 = 167600 B

    for (int v = threadIdx.x; v < NV; v += blockDim.x) {
        float x = tpts[3 * v + 0];
        float y = tpts[3 * v + 1];
        float z = tpts[3 * v + 2];
        float t2 = __fadd_rn(__fadd_rn(__fmul_rn(x, x), __fmul_rn(y, y)),
                             __fmul_rn(z, z));
        st[v] = make_float4(x, y, z, t2);
    }
    __syncthreads();

    int n = blockIdx.x * blockDim.x + threadIdx.x;

    float px = pts[3 * n + 0];
    float py = pts[3 * n + 1];
    float pz = pts[3 * n + 2];
    float p2 = __fadd_rn(__fadd_rn(__fmul_rn(px, px), __fmul_rn(py, py)),
                         __fmul_rn(pz, pz));

    float bd[KNN];     // best (smallest) d2, ascending
    int   bi[KNN];
#pragma unroll
    for (int k = 0; k < KNN; ++k) { bd[k] = INFINITY; bi[k] = 0; }

#pragma unroll 4
    for (int v = 0; v < NV; ++v) {
        float4 t = st[v];
        float cross = __fmaf_rn(pz, t.z,
                      __fmaf_rn(py, t.y,
                      __fmul_rn(px, t.x)));
        float d2 = __fmaf_rn(-2.0f, cross, __fadd_rn(p2, t.w));
        if (d2 < bd[KNN - 1]) {                 // rarely taken
            bd[KNN - 1] = d2; bi[KNN - 1] = v;
#pragma unroll
            for (int k = KNN - 1; k > 0; --k) {
                if (bd[k] < bd[k - 1]) {        // strict: stable for ties
                    float td_ = bd[k]; bd[k] = bd[k - 1]; bd[k - 1] = td_;
                    int   ti_ = bi[k]; bi[k] = bi[k - 1]; bi[k - 1] = ti_;
                }
            }
        }
    }

#pragma unroll
    for (int k = 0; k < KNN; ++k) {
        g_knn_idx[n * KNN + k] = bi[k];
        g_knn_d  [n * KNN + k] = fmaxf(bd[k], 0.0f);  // reference clamp
    }
}

// ---------------------------------------------------------------------------
// Kernel 2: epilogue. One warp = one point. Full reference formula.
// ---------------------------------------------------------------------------
extern "C" __global__ void __launch_bounds__(256)
epilogue_kernel(const float* __restrict__ lbs,   // (V,55)
                const float* __restrict__ vt,    // (V,16)
                float* __restrict__ out)         // [N dist | N*16 transform]
{
    int gwarp = (blockIdx.x * blockDim.x + threadIdx.x) >> 5;
    int lane  = threadIdx.x & 31;

    int   idx[KNN];
    float d[KNN];
#pragma unroll
    for (int k = 0; k < KNN; ++k) {
        idx[k] = g_knn_idx[gwarp * KNN + k];
        d[k]   = g_knn_d  [gwarp * KNN + k];
    }

    const float* w0row = lbs + (long)idx[0] * NJ;
    float w0a = w0row[lane];
    float w0b = (lane < NJ - 32) ? w0row[lane + 32] : 0.0f;

    float conf[KNN];
    conf[0] = 1.0f;
#pragma unroll
    for (int k = 1; k < KNN; ++k) {
        const float* wr = lbs + (long)idx[k] * NJ;
        float a = fabsf(wr[lane] - w0a);
        if (lane < NJ - 32) a += fabsf(wr[lane + 32] - w0b);
#pragma unroll
        for (int off = 16; off >= 1; off >>= 1)
            a += __shfl_xor_sync(0xFFFFFFFFu, a, off);
        conf[k] = (expf(-a * (1.0f / 0.02f)) > 0.9f) ? 1.0f : 0.0f;
    }

    float w[KNN];
    float wsum = 0.0f;
#pragma unroll
    for (int k = 0; k < KNN; ++k) {
        w[k] = expf(-d[k]) * conf[k];
        wsum += w[k];
    }
    float inv = 1.0f / wsum;

    float xd  = 0.0f;
    float acc = 0.0f;
#pragma unroll
    for (int k = 0; k < KNN; ++k) {
        float wk = w[k] * inv;
        xd = fmaf(wk, d[k], xd);
        if (lane < 16)
            acc = fmaf(wk, vt[(long)idx[k] * 16 + lane], acc);
    }

    if (lane == 0) out[gwarp] = xd;
    if (lane < 16) out[NPTS + gwarp * 16 + lane] = acc;
}

// ---------------------------------------------------------------------------
// Launch. Inputs: lbs_weights, verts_transform, points, template_points, K.
// ---------------------------------------------------------------------------
extern "C" void kernel_launch(void* const* d_in, const int* in_sizes, int n_in,
                              void* d_out, int out_size)
{
    const float* lbs  = (const float*)d_in[0];
    const float* vt   = (const float*)d_in[1];
    const float* pts  = (const float*)d_in[2];
    const float* tpts = (const float*)d_in[3];
    float* out = (float*)d_out;

    const int smem_bytes = NV * (int)sizeof(float4);   // 167600
    cudaFuncSetAttribute(knn_kernel,
                         cudaFuncAttributeMaxDynamicSharedMemorySize,
                         smem_bytes);

    knn_kernel<<<NPTS / 256, 256, smem_bytes>>>(pts, tpts);
    epilogue_kernel<<<(NPTS * 32) / 256, 256>>>(lbs, vt, out);
}

// round 4
// speedup vs baseline: 1.4932x; 1.4932x over previous
#include <cuda_runtime.h>
#include <cuda_bf16.h>
#include <math.h>

// Problem constants (fixed by setup_inputs)
#define NPTS 32768
#define NV   10475
#define NVP  10496          // NV padded to multiple of 64 (sentinels)
#define NJ   55
#define KNN  6
#define VBLK 64             // threshold refresh period
#define SEPS 1e-3f          // screening slack (>> 2e-5 rounding skew)

// Scratch (no cudaMalloc allowed).
__device__ int   g_knn_idx[NPTS * KNN];
__device__ float g_knn_d  [NPTS * KNN];

// ---------------------------------------------------------------------------
// Kernel 1: screened KNN.
// Hot loop: s = fma(pz,tz, fma(py,ty, fma(px,tx, -t2/2)))  (3 FFMA + LDS.128)
// Batch-of-8 max compared against a threshold that is STALE within each
// 64-template block -> no loop-carried dependency in the hot path.
// Rare path: exact reference-rounded d2 (identical to the R3-verified math):
//   cross = fma(pz,tz, fma(py,ty, fl(px*tx)))
//   d2    = fma(-2, cross, fl(p2 + t2)),  t2 = -2*w (exact)
// ---------------------------------------------------------------------------
extern "C" __global__ void __launch_bounds__(256, 1)
knn_kernel(const float* __restrict__ pts,      // (N,3)
           const float* __restrict__ tpts)     // (V,3)
{
    extern __shared__ float4 st[];   // NVP float4 = 167936 B

    for (int v = threadIdx.x; v < NVP; v += 256) {
        if (v < NV) {
            float x = tpts[3 * v + 0];
            float y = tpts[3 * v + 1];
            float z = tpts[3 * v + 2];
            float t2 = __fadd_rn(__fadd_rn(__fmul_rn(x, x), __fmul_rn(y, y)),
                                 __fmul_rn(z, z));
            st[v] = make_float4(x, y, z, -0.5f * t2);   // exact halving
        } else {
            st[v] = make_float4(0.0f, 0.0f, 0.0f, -INFINITY);  // sentinel
        }
    }
    __syncthreads();

    int n = blockIdx.x * blockDim.x + threadIdx.x;

    float px = pts[3 * n + 0];
    float py = pts[3 * n + 1];
    float pz = pts[3 * n + 2];
    float p2 = __fadd_rn(__fadd_rn(__fmul_rn(px, px), __fmul_rn(py, py)),
                         __fmul_rn(pz, pz));

    float bd[KNN];     // best (smallest) exact d2, ascending
    int   bi[KNN];
#pragma unroll
    for (int k = 0; k < KNN; ++k) { bd[k] = INFINITY; bi[k] = 0; }

    float s_thresh = -INFINITY;     // pass screen if s > s_thresh

#pragma unroll 1
    for (int vb = 0; vb < NVP; vb += VBLK) {
#pragma unroll 1
        for (int v8 = vb; v8 < vb + VBLK; v8 += 8) {
            float s[8];
#pragma unroll
            for (int i = 0; i < 8; ++i) {
                float4 t = st[v8 + i];
                s[i] = fmaf(pz, t.z, fmaf(py, t.y, fmaf(px, t.x, t.w)));
            }
            float m01 = fmaxf(s[0], s[1]);
            float m23 = fmaxf(s[2], s[3]);
            float m45 = fmaxf(s[4], s[5]);
            float m67 = fmaxf(s[6], s[7]);
            float m03 = fmaxf(m01, m23);
            float m47 = fmaxf(m45, m67);
            float m   = fmaxf(m03, m47);

            if (m > s_thresh) {     // rare after warmup
#pragma unroll
                for (int i = 0; i < 8; ++i) {
                    if (s[i] > s_thresh) {
                        float4 t = st[v8 + i];
                        float t2 = -2.0f * t.w;                 // exact
                        float cross = __fmaf_rn(pz, t.z,
                                      __fmaf_rn(py, t.y,
                                      __fmul_rn(px, t.x)));
                        float d2 = __fmaf_rn(-2.0f, cross,
                                             __fadd_rn(p2, t2));
                        if (d2 < bd[KNN - 1]) {
                            bd[KNN - 1] = d2; bi[KNN - 1] = v8 + i;
#pragma unroll
                            for (int k = KNN - 1; k > 0; --k) {
                                if (bd[k] < bd[k - 1]) {   // strict: tie-stable
                                    float td_ = bd[k]; bd[k] = bd[k-1]; bd[k-1] = td_;
                                    int   ti_ = bi[k]; bi[k] = bi[k-1]; bi[k-1] = ti_;
                                }
                            }
                        }
                    }
                }
            }
        }
        // Refresh stale threshold (d2 < bd[5]  <=>  s > (p2 - bd[5])/2)
        s_thresh = fmaf(-0.5f, bd[KNN - 1], 0.5f * p2) - SEPS;
    }

#pragma unroll
    for (int k = 0; k < KNN; ++k) {
        g_knn_idx[n * KNN + k] = bi[k];
        g_knn_d  [n * KNN + k] = fmaxf(bd[k], 0.0f);  // reference clamp
    }
}

// ---------------------------------------------------------------------------
// Kernel 2: epilogue. One warp = one point. Full reference formula.
// ---------------------------------------------------------------------------
extern "C" __global__ void __launch_bounds__(256)
epilogue_kernel(const float* __restrict__ lbs,   // (V,55)
                const float* __restrict__ vt,    // (V,16)
                float* __restrict__ out)         // [N dist | N*16 transform]
{
    int gwarp = (blockIdx.x * blockDim.x + threadIdx.x) >> 5;
    int lane  = threadIdx.x & 31;

    int   idx[KNN];
    float d[KNN];
#pragma unroll
    for (int k = 0; k < KNN; ++k) {
        idx[k] = g_knn_idx[gwarp * KNN + k];
        d[k]   = g_knn_d  [gwarp * KNN + k];
    }

    const float* w0row = lbs + (long)idx[0] * NJ;
    float w0a = w0row[lane];
    float w0b = (lane < NJ - 32) ? w0row[lane + 32] : 0.0f;

    float conf[KNN];
    conf[0] = 1.0f;
#pragma unroll
    for (int k = 1; k < KNN; ++k) {
        const float* wr = lbs + (long)idx[k] * NJ;
        float a = fabsf(wr[lane] - w0a);
        if (lane < NJ - 32) a += fabsf(wr[lane + 32] - w0b);
#pragma unroll
        for (int off = 16; off >= 1; off >>= 1)
            a += __shfl_xor_sync(0xFFFFFFFFu, a, off);
        conf[k] = (expf(-a * (1.0f / 0.02f)) > 0.9f) ? 1.0f : 0.0f;
    }

    float w[KNN];
    float wsum = 0.0f;
#pragma unroll
    for (int k = 0; k < KNN; ++k) {
        w[k] = expf(-d[k]) * conf[k];
        wsum += w[k];
    }
    float inv = 1.0f / wsum;

    float xd  = 0.0f;
    float acc = 0.0f;
#pragma unroll
    for (int k = 0; k < KNN; ++k) {
        float wk = w[k] * inv;
        xd = fmaf(wk, d[k], xd);
        if (lane < 16)
            acc = fmaf(wk, vt[(long)idx[k] * 16 + lane], acc);
    }

    if (lane == 0) out[gwarp] = xd;
    if (lane < 16) out[NPTS + gwarp * 16 + lane] = acc;
}

// ---------------------------------------------------------------------------
// Launch. Inputs: lbs_weights, verts_transform, points, template_points, K.
// ---------------------------------------------------------------------------
extern "C" void kernel_launch(void* const* d_in, const int* in_sizes, int n_in,
                              void* d_out, int out_size)
{
    const float* lbs  = (const float*)d_in[0];
    const float* vt   = (const float*)d_in[1];
    const float* pts  = (const float*)d_in[2];
    const float* tpts = (const float*)d_in[3];
    float* out = (float*)d_out;

    const int smem_bytes = NVP * (int)sizeof(float4);   // 167936
    cudaFuncSetAttribute(knn_kernel,
                         cudaFuncAttributeMaxDynamicSharedMemorySize,
                         smem_bytes);

    knn_kernel<<<NPTS / 256, 256, smem_bytes>>>(pts, tpts);
    epilogue_kernel<<<(NPTS * 32) / 256, 256>>>(lbs, vt, out);
}